// round 1
// baseline (speedup 1.0000x reference)
#include <cuda_runtime.h>
#include <cstdint>

#define NN 3072
#define PP 4
#define FF 64
#define INF_ 256
#define LALPHA 0.2f

// ---------------- device scratch (no runtime allocation allowed) ----------------
__device__ float g_Wh[NN * FF];        // [N, F]
__device__ float g_s1[NN];
__device__ float g_s2[NN];
__device__ float g_rs[PP * NN];        // row sums of e, per p
__device__ float g_cs[PP * NN];        // col sums of e, per p
__device__ float g_u[PP * NN];         // lamb - rs
__device__ float g_v[PP * NN];         // lamb - cs
__device__ float g_par[PP * 2];        // {inv_r, inv_lamb} per p
__device__ float g_e[(size_t)PP * NN * NN]; // fallback e storage if out buffer lacks room

// ---------------- kernel 0: zero the reduction buffers ----------------
__global__ void k_zero() {
    int i = blockIdx.x * blockDim.x + threadIdx.x;
    if (i < PP * NN) { g_rs[i] = 0.f; g_cs[i] = 0.f; }
}

// ---------------- kernel A: Wh = h @ W  (3072x256 @ 256x64) ----------------
__global__ void __launch_bounds__(256) k_wh(const float* __restrict__ h,
                                            const float* __restrict__ W) {
    __shared__ float hs[32][INF_];          // 32 KB
    int i0 = blockIdx.x * 32;
    int tid = threadIdx.x;
    // load 32 rows of h (8192 floats) via float4
    const float4* hg = (const float4*)(h + (size_t)i0 * INF_);
    float4* hs4 = (float4*)hs;
#pragma unroll
    for (int k = 0; k < 8; k++) hs4[tid + 256 * k] = hg[tid + 256 * k];
    __syncthreads();
    int f = tid & 63;
    int ir = tid >> 6;                      // 0..3 -> rows ir*8 .. ir*8+7
    float acc[8];
#pragma unroll
    for (int r = 0; r < 8; r++) acc[r] = 0.f;
    for (int k = 0; k < INF_; k++) {
        float wk = W[k * FF + f];
#pragma unroll
        for (int r = 0; r < 8; r++) acc[r] += hs[ir * 8 + r][k] * wk;
    }
#pragma unroll
    for (int r = 0; r < 8; r++)
        g_Wh[(size_t)(i0 + ir * 8 + r) * FF + f] = acc[r];
}

// ---------------- kernel B: s1 = Wh @ a[:F], s2 = Wh @ a[F:] ----------------
__global__ void k_s12(const float* __restrict__ a) {
    int wid = threadIdx.x >> 5;
    int lane = threadIdx.x & 31;
    int i = blockIdx.x * 8 + wid;
    float w0 = g_Wh[(size_t)i * FF + lane];
    float w1 = g_Wh[(size_t)i * FF + 32 + lane];
    float p1 = w0 * a[lane] + w1 * a[32 + lane];
    float p2 = w0 * a[FF + lane] + w1 * a[FF + 32 + lane];
#pragma unroll
    for (int o = 16; o > 0; o >>= 1) {
        p1 += __shfl_down_sync(0xffffffffu, p1, o);
        p2 += __shfl_down_sync(0xffffffffu, p2, o);
    }
    if (lane == 0) { g_s1[i] = p1; g_s2[i] = p2; }
}

// ---------------- kernel C: e = lrelu(s1_i + s2_j) * edge; row/col sums ----------------
__global__ void __launch_bounds__(256) k_pass1(const float* __restrict__ edge,
                                               float* __restrict__ e_out) {
    int p = blockIdx.y;
    int i0 = blockIdx.x * 16;
    int tid = threadIdx.x;
    const float4* s2v = (const float4*)g_s2;
    float4 s2r[3];
#pragma unroll
    for (int k = 0; k < 3; k++) s2r[k] = s2v[tid + 256 * k];
    float4 ca[3];
#pragma unroll
    for (int k = 0; k < 3; k++) ca[k] = make_float4(0.f, 0.f, 0.f, 0.f);

    const float4* eg = (const float4*)(edge + (size_t)p * NN * NN);
    float4* eo = (float4*)(e_out + (size_t)p * NN * NN);

    for (int r = 0; r < 16; r++) {
        int i = i0 + r;
        float s1i = g_s1[i];
        size_t rb = (size_t)i * (NN / 4);
        float rp = 0.f;
#pragma unroll
        for (int k = 0; k < 3; k++) {
            float4 ea = eg[rb + tid + 256 * k];
            float4 s2q = s2r[k];
            float4 ev; float x;
            x = s1i + s2q.x; x = x > 0.f ? x : LALPHA * x; ev.x = x * ea.x;
            x = s1i + s2q.y; x = x > 0.f ? x : LALPHA * x; ev.y = x * ea.y;
            x = s1i + s2q.z; x = x > 0.f ? x : LALPHA * x; ev.z = x * ea.z;
            x = s1i + s2q.w; x = x > 0.f ? x : LALPHA * x; ev.w = x * ea.w;
            eo[rb + tid + 256 * k] = ev;
            rp += (ev.x + ev.y) + (ev.z + ev.w);
            ca[k].x += ev.x; ca[k].y += ev.y; ca[k].z += ev.z; ca[k].w += ev.w;
        }
#pragma unroll
        for (int o = 16; o > 0; o >>= 1) rp += __shfl_down_sync(0xffffffffu, rp, o);
        if ((tid & 31) == 0) atomicAdd(&g_rs[p * NN + i], rp);
    }
#pragma unroll
    for (int k = 0; k < 3; k++) {
        int j = (tid + 256 * k) * 4;
        atomicAdd(&g_cs[p * NN + j + 0], ca[k].x);
        atomicAdd(&g_cs[p * NN + j + 1], ca[k].y);
        atomicAdd(&g_cs[p * NN + j + 2], ca[k].z);
        atomicAdd(&g_cs[p * NN + j + 3], ca[k].w);
    }
}

// ---------------- kernel D: per-p scalars lamb, r and u/v vectors ----------------
__global__ void k_scal() {
    int p = blockIdx.x;
    int tid = threadIdx.x; // 256
    __shared__ float smx[256], ssm[256];
    __shared__ float lambS;
    float mx = -1e30f, sm = 0.f;
    for (int k = tid; k < NN; k += 256) {
        float rv = g_rs[p * NN + k];
        float cv = g_cs[p * NN + k];
        mx = fmaxf(mx, fmaxf(rv, cv));
        sm += rv;
    }
    smx[tid] = mx; ssm[tid] = sm;
    __syncthreads();
    for (int s = 128; s > 0; s >>= 1) {
        if (tid < s) { smx[tid] = fmaxf(smx[tid], smx[tid + s]); ssm[tid] += ssm[tid + s]; }
        __syncthreads();
    }
    if (tid == 0) {
        float lamb = smx[0];
        float T = ssm[0];
        float r = (float)NN * lamb - T;
        g_par[p * 2 + 0] = 1.f / r;
        g_par[p * 2 + 1] = 1.f / lamb;   // normalizer S == lamb analytically
        lambS = lamb;
    }
    __syncthreads();
    float lamb = lambS;
    for (int k = tid; k < NN; k += 256) {
        g_u[p * NN + k] = lamb - g_rs[p * NN + k];
        g_v[p * NN + k] = lamb - g_cs[p * NN + k];
    }
}

// ---------------- kernel E: h' = attention @ Wh, elu, interleaved store ----------------
__global__ void __launch_bounds__(256) k_pass2(const float* __restrict__ e_in,
                                               float* __restrict__ out0) {
    constexpr int JT = 64;
    __shared__ float wh_s[JT][FF];    // 16 KB
    __shared__ float att_s[64][JT];   // 16 KB
    __shared__ float u_s[64];
    __shared__ float v_s[JT];

    int p = blockIdx.y;
    int i0 = blockIdx.x * 64;
    int tid = threadIdx.x;
    float inv_r = g_par[p * 2 + 0];
    float inv_l = g_par[p * 2 + 1];
    if (tid < 64) u_s[tid] = g_u[p * NN + i0 + tid];

    int fg = tid & 15, ig = tid >> 4;
    int f0 = fg * 4, it = ig * 4;
    unsigned long long acc[4][2];
#pragma unroll
    for (int r = 0; r < 4; r++) { acc[r][0] = 0ull; acc[r][1] = 0ull; }

    const float* ebase = e_in + (size_t)p * NN * NN + (size_t)i0 * NN;

    for (int jt = 0; jt < NN; jt += JT) {
        __syncthreads();
        {   // Wh tile: 64 x 64 floats = 1024 float4
            const float4* whg = (const float4*)(g_Wh + (size_t)jt * FF);
            float4* d = (float4*)wh_s;
#pragma unroll
            for (int k = 0; k < 4; k++) d[tid + 256 * k] = whg[tid + 256 * k];
        }
        if (tid < JT) v_s[tid] = g_v[p * NN + jt + tid];
        __syncthreads();
        // attention tile: 64 rows x 64 cols, computed on the fly from e
#pragma unroll
        for (int k = 0; k < 4; k++) {
            int idx = tid + 256 * k;
            int i = idx >> 4, j4 = idx & 15;
            float4 ev = *(const float4*)(ebase + (size_t)i * NN + jt + j4 * 4);
            float ui = u_s[i];
            float4 av;
            av.x = ev.x > 0.f ? (ev.x + ui * v_s[j4 * 4 + 0] * inv_r) * inv_l : ev.x;
            av.y = ev.y > 0.f ? (ev.y + ui * v_s[j4 * 4 + 1] * inv_r) * inv_l : ev.y;
            av.z = ev.z > 0.f ? (ev.z + ui * v_s[j4 * 4 + 2] * inv_r) * inv_l : ev.z;
            av.w = ev.w > 0.f ? (ev.w + ui * v_s[j4 * 4 + 3] * inv_r) * inv_l : ev.w;
            *(float4*)&att_s[i][j4 * 4] = av;
        }
        __syncthreads();
#pragma unroll 4
        for (int j = 0; j < JT; j++) {
            ulonglong2 wh2 = *(const ulonglong2*)&wh_s[j][f0];
#pragma unroll
            for (int r = 0; r < 4; r++) {
                float av = att_s[it + r][j];
                unsigned long long ap;
                asm("mov.b64 %0, {%1, %1};" : "=l"(ap) : "r"(__float_as_uint(av)));
                asm("fma.rn.f32x2 %0, %1, %2, %0;" : "+l"(acc[r][0]) : "l"(ap), "l"(wh2.x));
                asm("fma.rn.f32x2 %0, %1, %2, %0;" : "+l"(acc[r][1]) : "l"(ap), "l"(wh2.y));
            }
        }
    }
    // epilogue: out0[i, p*F + f] = elu(acc)
#pragma unroll
    for (int r = 0; r < 4; r++) {
        unsigned int lo, hi;
        float4 v;
        asm("mov.b64 {%0,%1}, %2;" : "=r"(lo), "=r"(hi) : "l"(acc[r][0]));
        v.x = __uint_as_float(lo); v.y = __uint_as_float(hi);
        asm("mov.b64 {%0,%1}, %2;" : "=r"(lo), "=r"(hi) : "l"(acc[r][1]));
        v.z = __uint_as_float(lo); v.w = __uint_as_float(hi);
        v.x = v.x > 0.f ? v.x : expm1f(v.x);
        v.y = v.y > 0.f ? v.y : expm1f(v.y);
        v.z = v.z > 0.f ? v.z : expm1f(v.z);
        v.w = v.w > 0.f ? v.w : expm1f(v.w);
        int i = i0 + it + r;
        *(float4*)(out0 + (size_t)i * (PP * FF) + p * FF + f0) = v;
    }
}

// ---------------- launch ----------------
extern "C" void kernel_launch(void* const* d_in, const int* in_sizes, int n_in,
                              void* d_out, int out_size) {
    const float* h    = (const float*)d_in[0];
    const float* edge = (const float*)d_in[1];
    const float* W    = (const float*)d_in[2];
    const float* a    = (const float*)d_in[3];
    float* out = (float*)d_out;

    // e destination: second output region if present, else device scratch
    float* e_dst;
    long long need = (long long)NN * PP * FF + (long long)PP * NN * NN;
    if ((long long)out_size >= need) {
        e_dst = out + (size_t)NN * PP * FF;
    } else {
        void* p = nullptr;
        cudaGetSymbolAddress(&p, g_e);
        e_dst = (float*)p;
    }

    k_zero<<<(PP * NN + 255) / 256, 256>>>();
    k_wh<<<NN / 32, 256>>>(h, W);
    k_s12<<<NN / 8, 256>>>(a);
    k_pass1<<<dim3(NN / 16, PP), 256>>>(edge, e_dst);
    k_scal<<<PP, 256>>>();
    k_pass2<<<dim3(NN / 64, PP), 256>>>(e_dst, out);
}

// round 4
// speedup vs baseline: 1.4844x; 1.4844x over previous
#include <cuda_runtime.h>
#include <cuda_bf16.h>
#include <cstdint>

#define NN 3072
#define PP 4
#define FF 64
#define INF_ 256
#define LALPHA 0.2f

// ---------------- device scratch ----------------
__device__ float g_Wh[NN * FF];
__device__ float g_s1[NN];
__device__ float g_s2[NN];
__device__ float g_rs[PP * NN];
__device__ float g_cs[PP * NN];
__device__ float g_u[PP * NN];          // (lamb - rs) * inv_r
__device__ float g_v[PP * NN];          // (lamb - cs) * inv_l
__device__ float g_par[PP * 2];         // [p*2] = inv_l
__device__ __nv_bfloat16 g_whT_h[FF * NN];   // B = Wh^T bf16 hi  [f][j]
__device__ __nv_bfloat16 g_whT_l[FF * NN];   // residual lo
__device__ float g_e[(size_t)PP * NN * NN];  // fallback e storage

__device__ __forceinline__ uint32_t smem_u32(const void* p) {
    uint32_t a;
    asm("{ .reg .u64 t; cvta.to.shared.u64 t, %1; cvt.u32.u64 %0, t; }" : "=r"(a) : "l"(p));
    return a;
}
__device__ __forceinline__ uint32_t swz(uint32_t o) { return o ^ ((o >> 3) & 0x70); }

// ---------------- kernel 0 ----------------
__global__ void k_zero() {
    int i = blockIdx.x * blockDim.x + threadIdx.x;
    if (i < PP * NN) { g_rs[i] = 0.f; g_cs[i] = 0.f; }
}

// ---------------- kernel A: Wh = h @ W ----------------
__global__ void __launch_bounds__(256) k_wh(const float* __restrict__ h,
                                            const float* __restrict__ W) {
    __shared__ float hs[32][INF_];
    int i0 = blockIdx.x * 32;
    int tid = threadIdx.x;
    const float4* hg = (const float4*)(h + (size_t)i0 * INF_);
    float4* hs4 = (float4*)hs;
#pragma unroll
    for (int k = 0; k < 8; k++) hs4[tid + 256 * k] = hg[tid + 256 * k];
    __syncthreads();
    int f = tid & 63;
    int ir = tid >> 6;
    float acc[8];
#pragma unroll
    for (int r = 0; r < 8; r++) acc[r] = 0.f;
    for (int k = 0; k < INF_; k++) {
        float wk = W[k * FF + f];
#pragma unroll
        for (int r = 0; r < 8; r++) acc[r] += hs[ir * 8 + r][k] * wk;
    }
#pragma unroll
    for (int r = 0; r < 8; r++)
        g_Wh[(size_t)(i0 + ir * 8 + r) * FF + f] = acc[r];
}

// ---------------- kernel A2: split WhT into bf16 hi/lo ----------------
__global__ void k_split() {
    int idx = blockIdx.x * 256 + threadIdx.x;  // idx = f*NN + j
    if (idx < FF * NN) {
        int f = idx / NN, j = idx - f * NN;
        float w = g_Wh[(size_t)j * FF + f];
        __nv_bfloat16 hb = __float2bfloat16(w);
        float lo = w - __bfloat162float(hb);
        g_whT_h[idx] = hb;
        g_whT_l[idx] = __float2bfloat16(lo);
    }
}

// ---------------- kernel B: s1, s2 ----------------
__global__ void k_s12(const float* __restrict__ a) {
    int wid = threadIdx.x >> 5;
    int lane = threadIdx.x & 31;
    int i = blockIdx.x * 8 + wid;
    float w0 = g_Wh[(size_t)i * FF + lane];
    float w1 = g_Wh[(size_t)i * FF + 32 + lane];
    float p1 = w0 * a[lane] + w1 * a[32 + lane];
    float p2 = w0 * a[FF + lane] + w1 * a[FF + 32 + lane];
#pragma unroll
    for (int o = 16; o > 0; o >>= 1) {
        p1 += __shfl_down_sync(0xffffffffu, p1, o);
        p2 += __shfl_down_sync(0xffffffffu, p2, o);
    }
    if (lane == 0) { g_s1[i] = p1; g_s2[i] = p2; }
}

// ---------------- kernel C: e + row/col sums ----------------
__global__ void __launch_bounds__(256) k_pass1(const float* __restrict__ edge,
                                               float* __restrict__ e_out) {
    int p = blockIdx.y;
    int i0 = blockIdx.x * 16;
    int tid = threadIdx.x;
    const float4* s2v = (const float4*)g_s2;
    float4 s2r[3];
#pragma unroll
    for (int k = 0; k < 3; k++) s2r[k] = s2v[tid + 256 * k];
    float4 ca[3];
#pragma unroll
    for (int k = 0; k < 3; k++) ca[k] = make_float4(0.f, 0.f, 0.f, 0.f);

    const float4* eg = (const float4*)(edge + (size_t)p * NN * NN);
    float4* eo = (float4*)(e_out + (size_t)p * NN * NN);

    for (int r = 0; r < 16; r++) {
        int i = i0 + r;
        float s1i = g_s1[i];
        size_t rb = (size_t)i * (NN / 4);
        float rp = 0.f;
#pragma unroll
        for (int k = 0; k < 3; k++) {
            float4 ea = eg[rb + tid + 256 * k];
            float4 s2q = s2r[k];
            float4 ev; float x;
            x = s1i + s2q.x; x = x > 0.f ? x : LALPHA * x; ev.x = x * ea.x;
            x = s1i + s2q.y; x = x > 0.f ? x : LALPHA * x; ev.y = x * ea.y;
            x = s1i + s2q.z; x = x > 0.f ? x : LALPHA * x; ev.z = x * ea.z;
            x = s1i + s2q.w; x = x > 0.f ? x : LALPHA * x; ev.w = x * ea.w;
            eo[rb + tid + 256 * k] = ev;
            rp += (ev.x + ev.y) + (ev.z + ev.w);
            ca[k].x += ev.x; ca[k].y += ev.y; ca[k].z += ev.z; ca[k].w += ev.w;
        }
#pragma unroll
        for (int o = 16; o > 0; o >>= 1) rp += __shfl_down_sync(0xffffffffu, rp, o);
        if ((tid & 31) == 0) atomicAdd(&g_rs[p * NN + i], rp);
    }
#pragma unroll
    for (int k = 0; k < 3; k++) {
        int j = (tid + 256 * k) * 4;
        atomicAdd(&g_cs[p * NN + j + 0], ca[k].x);
        atomicAdd(&g_cs[p * NN + j + 1], ca[k].y);
        atomicAdd(&g_cs[p * NN + j + 2], ca[k].z);
        atomicAdd(&g_cs[p * NN + j + 3], ca[k].w);
    }
}

// ---------------- kernel D: scalars + folded u/v ----------------
__global__ void k_scal() {
    int p = blockIdx.x;
    int tid = threadIdx.x;
    __shared__ float smx[256], ssm[256];
    __shared__ float lambS, invrS, invlS;
    float mx = -1e30f, sm = 0.f;
    for (int k = tid; k < NN; k += 256) {
        float rv = g_rs[p * NN + k];
        float cv = g_cs[p * NN + k];
        mx = fmaxf(mx, fmaxf(rv, cv));
        sm += rv;
    }
    smx[tid] = mx; ssm[tid] = sm;
    __syncthreads();
    for (int s = 128; s > 0; s >>= 1) {
        if (tid < s) { smx[tid] = fmaxf(smx[tid], smx[tid + s]); ssm[tid] += ssm[tid + s]; }
        __syncthreads();
    }
    if (tid == 0) {
        float lamb = smx[0];
        float r = (float)NN * lamb - ssm[0];
        lambS = lamb;
        invrS = 1.f / r;
        invlS = 1.f / lamb;           // analytic: tt.sum(axis=0)[0] == lamb
        g_par[p * 2] = invlS;
    }
    __syncthreads();
    float lamb = lambS, ir = invrS, il = invlS;
    for (int k = tid; k < NN; k += 256) {
        g_u[p * NN + k] = (lamb - g_rs[p * NN + k]) * ir;
        g_v[p * NN + k] = (lamb - g_cs[p * NN + k]) * il;
    }
}

// ---------------- kernel E: mma.sync split-bf16 GEMM  h' = att @ Wh ----------------
// block: 96 rows x (one p), 192 threads = 6 warps, warp w -> rows [w*16, w*16+16)
// j-loop in chunks of 64; B (Wh^T) staged in SMEM double-buffered; A built in regs.
#define JT 64

__device__ __forceinline__ void ldsm4(uint32_t& r0, uint32_t& r1, uint32_t& r2, uint32_t& r3,
                                      uint32_t addr) {
    asm volatile("ldmatrix.sync.aligned.m8n8.x4.shared.b16 {%0,%1,%2,%3}, [%4];"
                 : "=r"(r0), "=r"(r1), "=r"(r2), "=r"(r3) : "r"(addr));
}
#define MMA(c, a0, a1, a2, a3, b0, b1) \
    asm volatile("mma.sync.aligned.m16n8k16.row.col.f32.bf16.bf16.f32 " \
        "{%0,%1,%2,%3}, {%4,%5,%6,%7}, {%8,%9}, {%0,%1,%2,%3};" \
        : "+f"((c)[0]), "+f"((c)[1]), "+f"((c)[2]), "+f"((c)[3]) \
        : "r"(a0), "r"(a1), "r"(a2), "r"(a3), "r"(b0), "r"(b1))

__global__ void __launch_bounds__(192) k_pass2m(const float* __restrict__ e_in,
                                                float* __restrict__ out0) {
    __shared__ __nv_bfloat16 b_s[2][2][64 * 64];   // [buf][hi/lo] 8KB each = 32KB
    __shared__ float v_s[NN];                      // 12KB

    int tid = threadIdx.x, lane = tid & 31, w = tid >> 5;
    int p = blockIdx.y, i0 = blockIdx.x * 96;
    float inv_l = g_par[p * 2];

    for (int j = tid; j < NN; j += 192) v_s[j] = g_v[p * NN + j];

    int g = lane >> 2, q = (lane & 3) * 2;
    int row0 = i0 + w * 16 + g;
    float u0 = g_u[p * NN + row0];
    float u1 = g_u[p * NN + row0 + 8];
    const float* ep0 = e_in + (size_t)p * NN * NN + (size_t)row0 * NN;
    const float* ep1 = ep0 + (size_t)8 * NN;

    // ldmatrix per-lane static offset parts for B
    int brow = (lane & 7) + ((lane >> 1) & 8);   // +8 for lanes 16..31
    int bk = ((lane >> 3) & 1) * 8;              // +8 k for lanes 8-15, 24-31
    uint32_t bs_base0 = smem_u32(&b_s[0][0][0]);

    float c[8][4];
#pragma unroll
    for (int n = 0; n < 8; n++)
#pragma unroll
        for (int r = 0; r < 4; r++) c[n][r] = 0.f;

    __syncthreads();

    for (int ch = 0; ch < NN / JT; ch++) {
        int buf = ch & 1;
        int jt = ch * JT;
        // ---- stage B chunk (64 f-rows x 64 j) hi+lo, swizzled rows of 128B ----
        for (int s = tid; s < 512; s += 192) {
            int fr = s >> 3, col = s & 7;
            uint4 vh = *(const uint4*)(g_whT_h + (size_t)fr * NN + jt + col * 8);
            uint4 vl = *(const uint4*)(g_whT_l + (size_t)fr * NN + jt + col * 8);
            uint32_t off = swz((uint32_t)(fr * 128 + col * 16));
            *(uint4*)((char*)&b_s[buf][0][0] + off) = vh;
            *(uint4*)((char*)&b_s[buf][1][0] + off) = vl;
        }
        __syncthreads();

        // per-buffer stride 16384 B (hi at +0, lo at +8192) -- matches b_s layout
        uint32_t bh_base = bs_base0 + buf * 16384;
        uint32_t bl_base = bh_base + 8192;

#pragma unroll
        for (int ks = 0; ks < 4; ks++) {
            int kb = jt + ks * 16 + q;
            // ---- A fragments directly from e (registers) ----
            float2 e00 = *(const float2*)(ep0 + kb);
            float2 e10 = *(const float2*)(ep1 + kb);
            float2 e01 = *(const float2*)(ep0 + kb + 8);
            float2 e11 = *(const float2*)(ep1 + kb + 8);
            float2 vA = *(const float2*)&v_s[kb];
            float2 vB = *(const float2*)&v_s[kb + 8];
            float a00 = e00.x > 0.f ? fmaf(u0, vA.x, e00.x * inv_l) : e00.x;
            float a01 = e00.y > 0.f ? fmaf(u0, vA.y, e00.y * inv_l) : e00.y;
            float a10 = e10.x > 0.f ? fmaf(u1, vA.x, e10.x * inv_l) : e10.x;
            float a11 = e10.y > 0.f ? fmaf(u1, vA.y, e10.y * inv_l) : e10.y;
            float a02 = e01.x > 0.f ? fmaf(u0, vB.x, e01.x * inv_l) : e01.x;
            float a03 = e01.y > 0.f ? fmaf(u0, vB.y, e01.y * inv_l) : e01.y;
            float a12 = e11.x > 0.f ? fmaf(u1, vB.x, e11.x * inv_l) : e11.x;
            float a13 = e11.y > 0.f ? fmaf(u1, vB.y, e11.y * inv_l) : e11.y;
            uint32_t ah0, ah1, ah2, ah3, al0, al1, al2, al3;
            asm("cvt.rn.bf16x2.f32 %0, %1, %2;" : "=r"(ah0) : "f"(a01), "f"(a00));
            asm("cvt.rn.bf16x2.f32 %0, %1, %2;" : "=r"(ah1) : "f"(a11), "f"(a10));
            asm("cvt.rn.bf16x2.f32 %0, %1, %2;" : "=r"(ah2) : "f"(a03), "f"(a02));
            asm("cvt.rn.bf16x2.f32 %0, %1, %2;" : "=r"(ah3) : "f"(a13), "f"(a12));
            float r00 = a00 - __uint_as_float(ah0 << 16);
            float r01 = a01 - __uint_as_float(ah0 & 0xffff0000u);
            float r10 = a10 - __uint_as_float(ah1 << 16);
            float r11 = a11 - __uint_as_float(ah1 & 0xffff0000u);
            float r02 = a02 - __uint_as_float(ah2 << 16);
            float r03 = a03 - __uint_as_float(ah2 & 0xffff0000u);
            float r12 = a12 - __uint_as_float(ah3 << 16);
            float r13 = a13 - __uint_as_float(ah3 & 0xffff0000u);
            asm("cvt.rn.bf16x2.f32 %0, %1, %2;" : "=r"(al0) : "f"(r01), "f"(r00));
            asm("cvt.rn.bf16x2.f32 %0, %1, %2;" : "=r"(al1) : "f"(r11), "f"(r10));
            asm("cvt.rn.bf16x2.f32 %0, %1, %2;" : "=r"(al2) : "f"(r03), "f"(r02));
            asm("cvt.rn.bf16x2.f32 %0, %1, %2;" : "=r"(al3) : "f"(r13), "f"(r12));

            uint32_t lof = (uint32_t)(brow * 128 + (ks * 16 + bk) * 2);
#pragma unroll
            for (int np = 0; np < 4; np++) {
                uint32_t off = swz(lof + np * 2048);
                uint32_t bh0, bh1, bh2, bh3, bl0, bl1, bl2, bl3;
                ldsm4(bh0, bh1, bh2, bh3, bh_base + off);
                ldsm4(bl0, bl1, bl2, bl3, bl_base + off);
                MMA(c[2 * np],     ah0, ah1, ah2, ah3, bh0, bh1);
                MMA(c[2 * np],     al0, al1, al2, al3, bh0, bh1);
                MMA(c[2 * np],     ah0, ah1, ah2, ah3, bl0, bl1);
                MMA(c[2 * np + 1], ah0, ah1, ah2, ah3, bh2, bh3);
                MMA(c[2 * np + 1], al0, al1, al2, al3, bh2, bh3);
                MMA(c[2 * np + 1], ah0, ah1, ah2, ah3, bl2, bl3);
            }
        }
    }

    // ---- epilogue: elu + store ----
    float* o0 = out0 + (size_t)row0 * (PP * FF) + p * FF + q;
    float* o1 = o0 + (size_t)8 * (PP * FF);
#pragma unroll
    for (int n = 0; n < 8; n++) {
        float2 v0, v1;
        v0.x = c[n][0] > 0.f ? c[n][0] : expm1f(c[n][0]);
        v0.y = c[n][1] > 0.f ? c[n][1] : expm1f(c[n][1]);
        v1.x = c[n][2] > 0.f ? c[n][2] : expm1f(c[n][2]);
        v1.y = c[n][3] > 0.f ? c[n][3] : expm1f(c[n][3]);
        *(float2*)(o0 + n * 8) = v0;
        *(float2*)(o1 + n * 8) = v1;
    }
}

// ---------------- launch ----------------
extern "C" void kernel_launch(void* const* d_in, const int* in_sizes, int n_in,
                              void* d_out, int out_size) {
    const float* h    = (const float*)d_in[0];
    const float* edge = (const float*)d_in[1];
    const float* W    = (const float*)d_in[2];
    const float* a    = (const float*)d_in[3];
    float* out = (float*)d_out;

    float* e_dst;
    long long need = (long long)NN * PP * FF + (long long)PP * NN * NN;
    if ((long long)out_size >= need) {
        e_dst = out + (size_t)NN * PP * FF;
    } else {
        void* pe = nullptr;
        cudaGetSymbolAddress(&pe, g_e);
        e_dst = (float*)pe;
    }

    k_zero<<<(PP * NN + 255) / 256, 256>>>();
    k_wh<<<NN / 32, 256>>>(h, W);
    k_split<<<(FF * NN + 255) / 256, 256>>>();
    k_s12<<<NN / 8, 256>>>(a);
    k_pass1<<<dim3(NN / 16, PP), 256>>>(edge, e_dst);
    k_scal<<<PP, 256>>>();
    k_pass2m<<<dim3(NN / 96, PP), 192>>>(e_dst, out);
}